// round 5
// baseline (speedup 1.0000x reference)
#include <cuda_runtime.h>
#include <math.h>

// Problem constants
#define B    16
#define SQ   128
#define SK   256
#define HID  128
#define H    4
#define DK   32
#define DIM  64
#define OUT  128

typedef unsigned long long u64;

// ---- packed f32x2 helpers (Blackwell FFMA2 path; ptxas never auto-fuses) ----
__device__ __forceinline__ void ffma2(u64 &d, u64 a, u64 b) {
    asm("fma.rn.f32x2 %0, %1, %2, %3;" : "=l"(d) : "l"(a), "l"(b), "l"(d));
}
__device__ __forceinline__ u64 dup2(float x) {
    u64 r; asm("mov.b64 %0, {%1, %1};" : "=l"(r) : "f"(x)); return r;
}
__device__ __forceinline__ u64 pack2(float lo, float hi) {
    u64 r; asm("mov.b64 %0, {%1, %2};" : "=l"(r) : "f"(lo), "f"(hi)); return r;
}
__device__ __forceinline__ float2 unpack2(u64 v) {
    float2 f; asm("mov.b64 {%0, %1}, %2;" : "=f"(f.x), "=f"(f.y) : "l"(v)); return f;
}

// Intermediate scratch (no cudaMalloc allowed)
__device__ float g_qp[B * SQ * HID];
__device__ float g_kp[B * SK * HID];
__device__ float g_x [B * SQ * (H * DIM)];

// ---------------------------------------------------------------------------
// QK projection GEMM: C[M,128] = A[M,128] @ W[128,128]^T + bias
// 32x64 block tile, 128 threads, 4x4 per thread. Full K=128 staged in smem
// (one barrier), inner loop = 2 LDS.128 + 4 dup + 8 FFMA2 per kk.
// ---------------------------------------------------------------------------
#define PAS 36   // As pitch: [k][m], 36*4B rows (16B-aligned float4 reads)
#define PBS 68   // Bs pitch: [k][n]

__global__ __launch_bounds__(128) void qk_proj_kernel(
        const float* __restrict__ q,  const float* __restrict__ Wq,
        const float* __restrict__ bq, float* __restrict__ qp,
        const float* __restrict__ k,  const float* __restrict__ Wk,
        const float* __restrict__ bk, float* __restrict__ kp) {
    extern __shared__ float sm[];
    float* As = sm;                 // 128 * PAS
    float* Bs = sm + 128 * PAS;     // 128 * PBS
    const int t = threadIdx.x;

    const float *A, *W, *bias; float* C; int tile;
    if (blockIdx.x < 128) { A = q; W = Wq; bias = bq; C = qp; tile = blockIdx.x; }
    else                  { A = k; W = Wk; bias = bk; C = kp; tile = blockIdx.x - 128; }
    const int row0 = (tile >> 1) * 32;
    const int col0 = (tile & 1) * 64;

    // stage A (32 rows x 128 k) transposed -> As[k][m]
    {
        const int lm = t >> 2, kb = (t & 3) * 32;
        #pragma unroll
        for (int j = 0; j < 8; j++) {
            float4 v = *(const float4*)(A + (row0 + lm) * 128 + kb + j * 4);
            As[(kb + j * 4 + 0) * PAS + lm] = v.x;
            As[(kb + j * 4 + 1) * PAS + lm] = v.y;
            As[(kb + j * 4 + 2) * PAS + lm] = v.z;
            As[(kb + j * 4 + 3) * PAS + lm] = v.w;
        }
    }
    // stage W (64 n x 128 k) transposed -> Bs[k][n]
    {
        const int n = t >> 1, kb = (t & 1) * 64;
        #pragma unroll
        for (int j = 0; j < 16; j++) {
            float4 v = *(const float4*)(W + (col0 + n) * 128 + kb + j * 4);
            Bs[(kb + j * 4 + 0) * PBS + n] = v.x;
            Bs[(kb + j * 4 + 1) * PBS + n] = v.y;
            Bs[(kb + j * 4 + 2) * PBS + n] = v.z;
            Bs[(kb + j * 4 + 3) * PBS + n] = v.w;
        }
    }
    __syncthreads();

    const int ty = t >> 4;          // 0..7 -> rows ty*4..+3
    const int tx = t & 15;          // 0..15 -> cols tx*4..+3
    u64 acc[4][2];
    #pragma unroll
    for (int i = 0; i < 4; i++) { acc[i][0] = 0ull; acc[i][1] = 0ull; }

    #pragma unroll 16
    for (int kk = 0; kk < 128; kk++) {
        float4 a = *(const float4*)(As + kk * PAS + ty * 4);
        ulonglong2 bb = *(const ulonglong2*)(Bs + kk * PBS + tx * 4);
        u64 d0 = dup2(a.x), d1 = dup2(a.y), d2 = dup2(a.z), d3 = dup2(a.w);
        ffma2(acc[0][0], d0, bb.x); ffma2(acc[0][1], d0, bb.y);
        ffma2(acc[1][0], d1, bb.x); ffma2(acc[1][1], d1, bb.y);
        ffma2(acc[2][0], d2, bb.x); ffma2(acc[2][1], d2, bb.y);
        ffma2(acc[3][0], d3, bb.x); ffma2(acc[3][1], d3, bb.y);
    }

    const float4 bias4 = *(const float4*)(bias + col0 + tx * 4);
    #pragma unroll
    for (int i = 0; i < 4; i++) {
        float2 p0 = unpack2(acc[i][0]);
        float2 p1 = unpack2(acc[i][1]);
        float4 o;
        o.x = p0.x + bias4.x; o.y = p0.y + bias4.y;
        o.z = p1.x + bias4.z; o.w = p1.y + bias4.w;
        *(float4*)(C + (row0 + ty * 4 + i) * 128 + col0 + tx * 4) = o;
    }
}

// ---------------------------------------------------------------------------
// O projection GEMM: out[2048,128] = x[2048,256] @ Wo[128,256]^T + bo
// 16x64 tiles -> 256 blocks, 128 threads, 2(m-pair)x4 per thread.
// K=256 staged in two 128-k chunks.
// ---------------------------------------------------------------------------
#define PAO 20   // As pitch: [k][m], 16 m + pad

__global__ __launch_bounds__(128) void o_proj_kernel(
        const float* __restrict__ x,  const float* __restrict__ Wo,
        const float* __restrict__ bo, float* __restrict__ out) {
    extern __shared__ float sm[];
    float* As = sm;                 // 128 * PAO
    float* Bs = sm + 128 * PAO;     // 128 * PBS
    const int t = threadIdx.x;
    const int row0 = (blockIdx.x >> 1) * 16;
    const int col0 = (blockIdx.x & 1) * 64;
    const int ty = t >> 4;          // 0..7 -> row pair ty*2
    const int tx = t & 15;          // cols tx*4..+3

    u64 acc[4] = {0ull, 0ull, 0ull, 0ull};   // pairs along m

    #pragma unroll 1
    for (int kc = 0; kc < 2; kc++) {
        if (kc) __syncthreads();
        // stage A chunk (16 rows x 128 k) -> As[k][m]
        {
            const int lm = t >> 3, kb = (t & 7) * 16;
            #pragma unroll
            for (int j = 0; j < 4; j++) {
                float4 v = *(const float4*)(x + (row0 + lm) * 256 + kc * 128 + kb + j * 4);
                As[(kb + j * 4 + 0) * PAO + lm] = v.x;
                As[(kb + j * 4 + 1) * PAO + lm] = v.y;
                As[(kb + j * 4 + 2) * PAO + lm] = v.z;
                As[(kb + j * 4 + 3) * PAO + lm] = v.w;
            }
        }
        // stage W chunk (64 n x 128 k) -> Bs[k][n]
        {
            const int n = t >> 1, kb = (t & 1) * 64;
            #pragma unroll
            for (int j = 0; j < 16; j++) {
                float4 v = *(const float4*)(Wo + (col0 + n) * 256 + kc * 128 + kb + j * 4);
                Bs[(kb + j * 4 + 0) * PBS + n] = v.x;
                Bs[(kb + j * 4 + 1) * PBS + n] = v.y;
                Bs[(kb + j * 4 + 2) * PBS + n] = v.z;
                Bs[(kb + j * 4 + 3) * PBS + n] = v.w;
            }
        }
        __syncthreads();

        #pragma unroll 16
        for (int kk = 0; kk < 128; kk++) {
            u64 a2 = *(const u64*)(As + kk * PAO + ty * 2);
            float4 bv = *(const float4*)(Bs + kk * PBS + tx * 4);
            ffma2(acc[0], a2, dup2(bv.x));
            ffma2(acc[1], a2, dup2(bv.y));
            ffma2(acc[2], a2, dup2(bv.z));
            ffma2(acc[3], a2, dup2(bv.w));
        }
    }

    const float4 bias4 = *(const float4*)(bo + col0 + tx * 4);
    float2 p0 = unpack2(acc[0]), p1 = unpack2(acc[1]);
    float2 p2 = unpack2(acc[2]), p3 = unpack2(acc[3]);
    float4 o0, o1;
    o0.x = p0.x + bias4.x; o0.y = p1.x + bias4.y; o0.z = p2.x + bias4.z; o0.w = p3.x + bias4.w;
    o1.x = p0.y + bias4.x; o1.y = p1.y + bias4.y; o1.z = p2.y + bias4.z; o1.w = p3.y + bias4.w;
    *(float4*)(out + (row0 + ty * 2 + 0) * 128 + col0 + tx * 4) = o0;
    *(float4*)(out + (row0 + ty * 2 + 1) * 128 + col0 + tx * 4) = o1;
}

// ---------------------------------------------------------------------------
// Fused masked attention. Grid: B*H*(SQ/32) = 256 blocks, 256 threads.
// Phase 1: e[k][q] = exp(q·k / sqrt(DK)), packed-pair dots (16 FFMA2/dot).
// Phase 2: (num|den) = e @ (m*v | m), pair = (num,den), 8 FFMA2 per k-step.
// ---------------------------------------------------------------------------
#define QT 32
#define EP 36    // e_t pitch [k][q]
#define KP 36    // staged K pitch [k][dk]

__global__ __launch_bounds__(256) void attn_kernel(
        const float* __restrict__ qp,
        const float* __restrict__ kp,
        const float* __restrict__ value,
        const int*   __restrict__ mask,
        float* __restrict__ xout) {
    extern __shared__ float sm[];
    float* q_s = sm;                        // 32*32   = 1024
    float* e_t = sm + QT * 32;              // 256*36  = 9216
    float* buf = e_t + SK * EP;             // 256*36  = 9216 (k-tile, then vm)
    float4* vm4 = (float4*)buf;             // phase-2 view: [64][32] float4

    const int blk = blockIdx.x;
    const int qt  = blk & 3;
    const int h   = (blk >> 2) & 3;
    const int b   = blk >> 4;
    const int q0  = qt * QT;
    const int tid = threadIdx.x;

    // stage Q tile (head slice)
    for (int idx = tid; idx < QT * 32; idx += 256) {
        int r = idx >> 5, i = idx & 31;
        q_s[idx] = qp[(b * SQ + q0 + r) * HID + h * DK + i];
    }
    // stage K tile, pitch 36
    for (int idx = tid; idx < SK * 32; idx += 256) {
        int kk = idx >> 5, i = idx & 31;
        buf[kk * KP + i] = kp[(b * SK + kk) * HID + h * DK + i];
    }
    __syncthreads();

    // Phase 1: one thread per k column -> e_t[k][q]
    {
        const int kk = tid;
        u64 k2[16];
        #pragma unroll
        for (int i = 0; i < 8; i++) {
            float4 v = *(const float4*)(buf + kk * KP + i * 4);
            k2[i * 2 + 0] = pack2(v.x, v.y);
            k2[i * 2 + 1] = pack2(v.z, v.w);
        }
        const float scale = 0.17677669529663687f;   // 1/sqrt(32)
        #pragma unroll 4
        for (int r = 0; r < QT; r++) {
            u64 acc2 = 0ull;
            #pragma unroll
            for (int i = 0; i < 16; i++) {
                u64 q2 = *(const u64*)(q_s + r * 32 + i * 2);   // broadcast LDS.64
                ffma2(acc2, q2, k2[i]);
            }
            float2 s = unpack2(acc2);
            e_t[kk * EP + r] = __expf((s.x + s.y) * scale);
        }
    }

    // Phase 2: warp qy = tid>>5 owns 4 q rows; lane dx = tid&31 owns d-pair
    const int qy = tid >> 5;
    const int dx = tid & 31;
    u64 accp[4][2];
    #pragma unroll
    for (int i = 0; i < 4; i++) { accp[i][0] = 0ull; accp[i][1] = 0ull; }

    #pragma unroll 1
    for (int c = 0; c < 4; c++) {
        __syncthreads();                    // prev chunk consumed / phase-1 buf reads done
        #pragma unroll
        for (int it = 0; it < 8; it++) {
            int item = tid + it * 256;
            int lk = item >> 5, d2 = item & 31;
            int gbase = (b * SK + c * 64 + lk) * DIM + d2 * 2;
            float2 v = *(const float2*)(value + gbase);
            int2  mm = *(const int2*)(mask + gbase);
            float4 w;
            w.x = mm.x ? v.x : 0.f;  w.y = mm.x ? 1.f : 0.f;
            w.z = mm.y ? v.y : 0.f;  w.w = mm.y ? 1.f : 0.f;
            vm4[lk * 32 + d2] = w;
        }
        __syncthreads();

        #pragma unroll 8
        for (int kk = 0; kk < 64; kk++) {
            float4 ev = *(const float4*)(e_t + (c * 64 + kk) * EP + qy * 4);  // broadcast
            ulonglong2 w = *(const ulonglong2*)(vm4 + kk * 32 + dx);
            u64 e0 = dup2(ev.x), e1 = dup2(ev.y), e2 = dup2(ev.z), e3 = dup2(ev.w);
            ffma2(accp[0][0], e0, w.x); ffma2(accp[0][1], e0, w.y);
            ffma2(accp[1][0], e1, w.x); ffma2(accp[1][1], e1, w.y);
            ffma2(accp[2][0], e2, w.x); ffma2(accp[2][1], e2, w.y);
            ffma2(accp[3][0], e3, w.x); ffma2(accp[3][1], e3, w.y);
        }
    }

    float num[4][2], den[4][2];
    #pragma unroll
    for (int i = 0; i < 4; i++) {
        float2 p = unpack2(accp[i][0]); num[i][0] = p.x; den[i][0] = p.y;
        p = unpack2(accp[i][1]);        num[i][1] = p.x; den[i][1] = p.y;
    }

    // Fallback for all-masked channel (softmax over uniform -NEG -> mean(value))
    bool bad = false;
    #pragma unroll
    for (int i = 0; i < 4; i++)
        if (den[i][0] == 0.f || den[i][1] == 0.f) bad = true;
    float vs0 = 0.f, vs1 = 0.f;
    if (bad) {
        for (int kk = 0; kk < SK; kk++) {
            float2 v = *(const float2*)(value + (b * SK + kk) * DIM + dx * 2);
            vs0 += v.x; vs1 += v.y;
        }
        vs0 *= (1.0f / 256.0f); vs1 *= (1.0f / 256.0f);
    }

    #pragma unroll
    for (int i = 0; i < 4; i++) {
        int r = qy * 4 + i;
        float2 o;
        o.x = (den[i][0] > 0.f) ? (num[i][0] / den[i][0]) : vs0;
        o.y = (den[i][1] > 0.f) ? (num[i][1] / den[i][1]) : vs1;
        *(float2*)(xout + (b * SQ + q0 + r) * (H * DIM) + h * DIM + dx * 2) = o;
    }
}

// ---------------------------------------------------------------------------
extern "C" void kernel_launch(void* const* d_in, const int* in_sizes, int n_in,
                              void* d_out, int out_size) {
    const float* query = (const float*)d_in[0];
    const float* key   = (const float*)d_in[1];
    const float* value = (const float*)d_in[2];
    const int*   mask  = (const int*)  d_in[3];
    const float* Wq    = (const float*)d_in[4];
    const float* bq    = (const float*)d_in[5];
    const float* Wk    = (const float*)d_in[6];
    const float* bk    = (const float*)d_in[7];
    const float* Wo    = (const float*)d_in[8];
    const float* bo    = (const float*)d_in[9];
    float* out = (float*)d_out;

    float* qp; cudaGetSymbolAddress((void**)&qp, g_qp);
    float* kp; cudaGetSymbolAddress((void**)&kp, g_kp);
    float* xb; cudaGetSymbolAddress((void**)&xb, g_x);

    const int smem_qk   = (128 * PAS + 128 * PBS) * (int)sizeof(float);     // 53.2 KB
    const int smem_o    = (128 * PAO + 128 * PBS) * (int)sizeof(float);     // 45.1 KB
    const int smem_attn = (QT * 32 + SK * EP + SK * KP) * (int)sizeof(float); // 77.8 KB

    cudaFuncSetAttribute(qk_proj_kernel, cudaFuncAttributeMaxDynamicSharedMemorySize, smem_qk);
    cudaFuncSetAttribute(o_proj_kernel,  cudaFuncAttributeMaxDynamicSharedMemorySize, smem_o);
    cudaFuncSetAttribute(attn_kernel,    cudaFuncAttributeMaxDynamicSharedMemorySize, smem_attn);

    // Q (2048x128x128) + K (4096x128x128) projection: 128 + 256 blocks
    qk_proj_kernel<<<384, 128, smem_qk>>>(query, Wq, bq, qp, key, Wk, bk, kp);
    // fused attention: 256 blocks
    attn_kernel<<<B * H * (SQ / QT), 256, smem_attn>>>(qp, kp, value, mask, xb);
    // output projection: 2048x128x256, 256 blocks
    o_proj_kernel<<<256, 128, smem_o>>>(xb, Wo, bo, out);
}